// round 16
// baseline (speedup 1.0000x reference)
#include <cuda_runtime.h>
#include <cuda_fp16.h>
#include <math.h>
#include <stdint.h>

#define B 16
#define CIN 512
#define COUT 512
#define HH 64
#define WW 64
#define SS 512
#define SCALE2 (1.0f / 4608.0f)

// ---------------- scratch (__device__ globals) ----------------
__device__ float g_s[B * CIN];
__device__ float g_demod[B * COUT];
__device__ float g_wsq[COUT * CIN];
// modulated fp16 input, chunk-major, plane-major rows:
// [b][chunk(32)][yp(66)][j(8)][px(72)]; word = half2(ci 2j, ci 2j+1) at pixel px
// px: 0 and 65 are halo zeros, 66..71 pad. row = 576 words.
__device__ __align__(16) uint32_t g_inh[(size_t)B * 32 * 66 * 576];
// fp16 weights in per-thread A-fragment order:
// [mt(4)][chunk(32)][tap(9)][wm(2)][mtile(4)][lane(32)][j(4)] uint32 (half2 ci pair)
__device__ __align__(16) uint32_t g_wfA[4 * 32 * 9 * 2 * 4 * 128];

// ---------------- PTX helpers ----------------
__device__ __forceinline__ uint32_t smem_u32(const void* p) {
    uint32_t a;
    asm("{ .reg .u64 t; cvta.to.shared.u64 t, %1; cvt.u32.u64 %0, t; }" : "=r"(a) : "l"(p));
    return a;
}
#define MBAR_INIT(a, n) asm volatile("mbarrier.init.shared.b64 [%0], %1;" :: "r"(a), "r"(n) : "memory")
#define MBAR_EXPECT(a, tx) asm volatile("mbarrier.arrive.expect_tx.shared.b64 _, [%0], %1;" :: "r"(a), "r"(tx) : "memory")
#define MBAR_WAIT(a, ph) do {                                                             \
    uint32_t _m = (a), _p = (ph);                                                         \
    asm volatile("{ .reg .pred P; WL%=:\n\t"                                              \
        "mbarrier.try_wait.parity.acquire.cta.shared::cta.b64 P, [%0], %1, 0x989680;\n\t" \
        "@P bra.uni WD%=;\n\t bra.uni WL%=;\n\t WD%=: }" :: "r"(_m), "r"(_p) : "memory"); \
} while (0)
#define FENCE_ASYNC() asm volatile("fence.proxy.async.shared::cta;" ::: "memory")
#define BULK_CP(dst, src, sz, mb)                                                              \
    asm volatile("cp.async.bulk.shared::cta.global.mbarrier::complete_tx::bytes [%0], [%1], %2, [%3];" \
        :: "r"(dst), "l"(src), "r"(sz), "r"(mb) : "memory")
#define MMA_F16(d, a, b0v, b1v)                                                            \
    asm volatile(                                                                          \
        "mma.sync.aligned.m16n8k16.row.col.f32.f16.f16.f32 "                               \
        "{%0,%1,%2,%3}, {%4,%5,%6,%7}, {%8,%9}, {%0,%1,%2,%3};"                            \
        : "+f"(d[0]), "+f"(d[1]), "+f"(d[2]), "+f"(d[3])                                   \
        : "r"(a.x), "r"(a.y), "r"(a.z), "r"(a.w), "r"(b0v), "r"(b1v))

// -------- prep 1: style (z=0) | wsq (z=1) | wfA 9-tap-per-thread (z=2) ------
__global__ void k_prep1(const float* __restrict__ style, const float* __restrict__ mod_w,
                        const float* __restrict__ mod_b, const float* __restrict__ weight) {
    if (blockIdx.z == 0) {
        __shared__ float ss[SS];
        const int b = blockIdx.x, lane = threadIdx.x & 31, warp = threadIdx.x >> 5;
        const int ci = blockIdx.y * 8 + warp;
        for (int i = threadIdx.x; i < SS; i += 256) ss[i] = style[b * SS + i];
        __syncthreads();
        const float* wr = mod_w + (size_t)ci * SS;
        float p = 0.f;
        #pragma unroll 4
        for (int j = lane; j < SS; j += 32) p = fmaf(wr[j], ss[j], p);
        #pragma unroll
        for (int o = 16; o > 0; o >>= 1) p += __shfl_xor_sync(0xffffffffu, p, o);
        if (lane == 0) g_s[b * CIN + ci] = p + mod_b[ci];
    } else if (blockIdx.z == 1) {
        int idx = (blockIdx.x * 64 + blockIdx.y) * 256 + threadIdx.x;  // 0..262143
        const float* w = weight + (size_t)idx * 9;
        float s = 0.f;
        #pragma unroll
        for (int k = 0; k < 9; k++) s = fmaf(w[k], w[k], s);
        g_wsq[idx] = s;
    } else {
        // wfA: one thread = one (co, ci-pair), all 9 taps.
        int bid = blockIdx.x * 64 + blockIdx.y;          // 0..1023, need < 512
        if (bid >= 512) return;
        int idx = bid * 256 + threadIdx.x;               // 0..131071
        int j     = idx & 3;
        int lane  = (idx >> 2) & 31;
        int mtile = (idx >> 7) & 3;
        int wm    = (idx >> 9) & 1;
        int chunk = (idx >> 10) & 31;
        int mt    = idx >> 15;
        int g = lane >> 2, tt = lane & 3;
        int co = mt * 128 + wm * 64 + mtile * 16 + g + (j & 1) * 8;
        int ci = chunk * 16 + 2 * tt + (j >> 1) * 8;
        const float* wp = weight + ((size_t)co * CIN + ci) * 9;
        float w0[9], w1[9];
        #pragma unroll
        for (int t = 0; t < 9; t++) w0[t] = __ldg(wp + t);
        #pragma unroll
        for (int t = 0; t < 9; t++) w1[t] = __ldg(wp + 9 + t);
        uint32_t base = ((uint32_t)(mt * 32 + chunk) * 9) * 1024
                        + wm * 512 + mtile * 128 + lane * 4 + j;
        #pragma unroll
        for (int t = 0; t < 9; t++) {
            __half2 h = __floats2half2_rn(w0[t], w1[t]);
            g_wfA[base + (uint32_t)t * 1024] = *(uint32_t*)&h;
        }
    }
}

// -------- prep 2: k_inh plane-major (z<16) | demod (z==16, 1024 blocks) -----
__global__ void k_prep2(const float* __restrict__ input) {
    if (blockIdx.z == 16) {
        // demod: 1024 active blocks x 8 warps = 8192 (b,co) warps
        int bid = blockIdx.y * 66 + blockIdx.x;       // 0..2111
        if (bid >= 1024) return;
        int wid = bid * 8 + (threadIdx.x >> 5);       // 0..8191
        int lane = threadIdx.x & 31;
        int b = wid >> 9, co = wid & 511;
        const float* wsq = g_wsq + (size_t)co * CIN;
        const float* sr = g_s + (size_t)b * CIN;
        float p = 0.f;
        #pragma unroll 4
        for (int j = lane; j < CIN; j += 32) { float sv = sr[j]; p = fmaf(wsq[j], sv * sv, p); }
        #pragma unroll
        for (int o = 16; o > 0; o >>= 1) p += __shfl_xor_sync(0xffffffffu, p, o);
        if (lane == 0) g_demod[b * COUT + co] = rsqrtf(SCALE2 * p + 1e-8f);
        return;
    }
    // k_inh: modulated input -> fp16 plane-major [j(8)][px(72)] rows
    __shared__ float sm[16][64];
    const int yp = blockIdx.x;      // 0..65 (rows 0 and 65 are zero borders)
    const int chunk = blockIdx.y;   // 0..31
    const int b = blockIdx.z;       // 0..15
    const int tid = threadIdx.x;
    uint32_t* dst = g_inh + (((size_t)(b * 32 + chunk) * 66 + yp) * 576);
    const bool border = (yp == 0 || yp == 65);

    if (!border) {
        const int y = yp - 1;
        // one float4 load per thread: 16 ci x 16 xq covers 16x64 floats
        const int ci = tid >> 4, xq = tid & 15;
        const float sv = __ldg(g_s + b * CIN + chunk * 16 + ci);
        const float4 v = *(const float4*)(input
            + (((size_t)(b * CIN + chunk * 16 + ci)) << 12) + y * 64 + xq * 4);
        sm[ci][xq * 4 + 0] = v.x * sv;
        sm[ci][xq * 4 + 1] = v.y * sv;
        sm[ci][xq * 4 + 2] = v.z * sv;
        sm[ci][xq * 4 + 3] = v.w * sv;
        __syncthreads();
    }
    // one uint4 store per thread: 144 uint4 = 8 j-planes x 18
    if (tid < 144) {
        const int j = tid / 18, q = tid - j * 18;
        uint32_t w[4];
        #pragma unroll
        for (int k = 0; k < 4; k++) {
            const int px = q * 4 + k;
            w[k] = 0u;
            if (!border && px >= 1 && px <= 64) {
                __half2 h = __floats2half2_rn(sm[2 * j][px - 1], sm[2 * j + 1][px - 1]);
                w[k] = *(uint32_t*)&h;
            }
        }
        *(uint4*)(dst + j * 72 + q * 4) = make_uint4(w[0], w[1], w[2], w[3]);
    }
}

// ---------------- main conv: fp16 mma.sync implicit GEMM (champion core) ----
// CTA: 128 co (mt) x 128 px (2 rows x 64 cols), 256 threads, 8 warps 2m x 4n.
// B rows plane-major [j(8)][px(72)]: bank = (8tt + g) mod 32 -> conflict-free.
#define NCHUNK 32
#define A_SLAB 36864               // 9*2*4*128*4 bytes
#define B_SLAB 9216                // 4 rows * 576 words * 4B
#define OFF_A 64
#define OFF_B (OFF_A + 2 * A_SLAB)          // 73792
#define SMEM_TOTAL (OFF_B + 2 * B_SLAB)     // 92224

__global__ void __launch_bounds__(256, 2)
k_conv(float* __restrict__ out) {
    extern __shared__ char smem[];
    const uint32_t sb = smem_u32(smem);
    const int tid = threadIdx.x, lane = tid & 31, wid = tid >> 5;
    const int wm = wid >> 2, wn = wid & 3;
    const int yl = wn >> 1, xw = (wn & 1) * 32;
    const int g = lane >> 2, tt = lane & 3;

    const int mt = blockIdx.x;
    const int y0 = blockIdx.y * 2;
    const int b  = blockIdx.z;

    if (tid == 0) { MBAR_INIT(sb + 0, 1); MBAR_INIT(sb + 8, 1); }
    __syncthreads();

    const uint32_t* gA = g_wfA + (size_t)mt * 32 * 9216;
    const uint32_t* gB = g_inh + (size_t)b * 32 * 66 * 576;

    if (tid == 0) {
        FENCE_ASYNC();
        #pragma unroll
        for (int k = 0; k < 2; k++) {
            uint32_t mb = sb + k * 8;
            MBAR_EXPECT(mb, A_SLAB + B_SLAB);
            BULK_CP(sb + OFF_A + k * A_SLAB, (const void*)(gA + (size_t)k * 9216), A_SLAB, mb);
            BULK_CP(sb + OFF_B + k * B_SLAB, (const void*)(gB + ((size_t)k * 66 + y0) * 576), B_SLAB, mb);
        }
    }

    float acc[4][4][4];
    #pragma unroll
    for (int m = 0; m < 4; m++)
        #pragma unroll
        for (int n = 0; n < 4; n++)
            #pragma unroll
            for (int c = 0; c < 4; c++) acc[m][n][c] = 0.f;

    for (int c = 0; c < NCHUNK; c++) {
        MBAR_WAIT(sb + (c & 1) * 8, (c >> 1) & 1);
        const uint32_t* sA = (const uint32_t*)(smem + OFF_A + (c & 1) * A_SLAB);
        const uint32_t* sB = (const uint32_t*)(smem + OFF_B + (c & 1) * B_SLAB);

        #pragma unroll
        for (int tap = 0; tap < 9; tap++) {
            const int dy = tap / 3, dx = tap % 3;
            const int r = yl + dy;
            const uint32_t* ap = sA + (tap * 2 + wm) * 512 + lane * 4;
            uint4 A0 = *(const uint4*)(ap);
            uint4 A1 = *(const uint4*)(ap + 128);
            uint4 A2 = *(const uint4*)(ap + 256);
            uint4 A3 = *(const uint4*)(ap + 384);
            // plane-major: b0 at j=tt, b1 at j=tt+4 (+288 words)
            const uint32_t* bp = sB + r * 576 + tt * 72 + (xw + dx + g);
            #pragma unroll
            for (int nf = 0; nf < 4; nf++) {
                uint32_t b0 = bp[nf * 8];
                uint32_t b1 = bp[nf * 8 + 288];
                MMA_F16(acc[0][nf], A0, b0, b1);
                MMA_F16(acc[1][nf], A1, b0, b1);
                MMA_F16(acc[2][nf], A2, b0, b1);
                MMA_F16(acc[3][nf], A3, b0, b1);
            }
        }
        __syncthreads();
        if (tid == 0 && c + 2 < NCHUNK) {
            const int k = c + 2;
            uint32_t mb = sb + (k & 1) * 8;
            MBAR_EXPECT(mb, A_SLAB + B_SLAB);
            BULK_CP(sb + OFF_A + (k & 1) * A_SLAB, (const void*)(gA + (size_t)k * 9216), A_SLAB, mb);
            BULK_CP(sb + OFF_B + (k & 1) * B_SLAB, (const void*)(gB + ((size_t)k * 66 + y0) * 576), B_SLAB, mb);
        }
    }

    // ---- epilogue: scale * demod, float2 stores ----
    const float scale = rsqrtf(4608.0f);
    const int y = y0 + yl;
    #pragma unroll
    for (int im = 0; im < 4; im++) {
        const int coA = mt * 128 + wm * 64 + im * 16 + g;
        const float fA = g_demod[b * COUT + coA] * scale;
        const float fB = g_demod[b * COUT + coA + 8] * scale;
        const size_t base = ((((size_t)b * COUT + coA) << 6) + y) << 6;
        #pragma unroll
        for (int nf = 0; nf < 4; nf++) {
            const int x = xw + nf * 8 + 2 * tt;
            float2 lo = make_float2(acc[im][nf][0] * fA, acc[im][nf][1] * fA);
            float2 hi = make_float2(acc[im][nf][2] * fB, acc[im][nf][3] * fB);
            *(float2*)(out + base + x) = lo;
            *(float2*)(out + base + ((size_t)8 << 12) + x) = hi;   // co+8 plane
        }
    }
}

// ---------------------------------------------------------------------------
extern "C" void kernel_launch(void* const* d_in, const int* in_sizes, int n_in,
                              void* d_out, int out_size) {
    const float* input  = (const float*)d_in[0];
    const float* style  = (const float*)d_in[1];
    const float* weight = (const float*)d_in[2];
    const float* mod_w  = (const float*)d_in[3];
    const float* mod_b  = (const float*)d_in[4];
    float* out = (float*)d_out;

    static int smem_set = 0;
    if (!smem_set) {
        cudaFuncSetAttribute(k_conv, cudaFuncAttributeMaxDynamicSharedMemorySize, SMEM_TOTAL);
        smem_set = 1;
    }

    k_prep1<<<dim3(16, 64, 3), 256>>>(style, mod_w, mod_b, weight);
    k_prep2<<<dim3(66, 32, 17), 256>>>(input);
    k_conv<<<dim3(4, 32, 16), 256, SMEM_TOTAL>>>(out);
}

// round 17
// speedup vs baseline: 1.5643x; 1.5643x over previous
#include <cuda_runtime.h>
#include <cuda_fp16.h>
#include <math.h>
#include <stdint.h>

#define B 16
#define CIN 512
#define COUT 512
#define HH 64
#define WW 64
#define SS 512
#define SCALE2 (1.0f / 4608.0f)

// ---------------- scratch (__device__ globals) ----------------
__device__ float g_s[B * CIN];
__device__ float g_demod[B * COUT];
__device__ float g_wsq[COUT * CIN];
// modulated fp16 input, chunk-major, padded halo, 12-word pixel rows:
// [b][chunk(32)][yp(66)][xh(66)][word(12)]; word j<8 = ciPair j, j>=8 pad
__device__ __align__(16) uint32_t g_inh[(size_t)B * 32 * 66 * 792];
// fp16 weights in per-thread A-fragment order:
// [mt(4)][chunk(32)][tap(9)][wm(2)][mtile(4)][lane(32)][j(4)] uint32 (half2 ci pair)
__device__ __align__(16) uint32_t g_wfA[4 * 32 * 9 * 2 * 4 * 128];

// ---------------- PTX helpers ----------------
__device__ __forceinline__ uint32_t smem_u32(const void* p) {
    uint32_t a;
    asm("{ .reg .u64 t; cvta.to.shared.u64 t, %1; cvt.u32.u64 %0, t; }" : "=r"(a) : "l"(p));
    return a;
}
#define MBAR_INIT(a, n) asm volatile("mbarrier.init.shared.b64 [%0], %1;" :: "r"(a), "r"(n) : "memory")
#define MBAR_EXPECT(a, tx) asm volatile("mbarrier.arrive.expect_tx.shared.b64 _, [%0], %1;" :: "r"(a), "r"(tx) : "memory")
#define MBAR_WAIT(a, ph) do {                                                             \
    uint32_t _m = (a), _p = (ph);                                                         \
    asm volatile("{ .reg .pred P; WL%=:\n\t"                                              \
        "mbarrier.try_wait.parity.acquire.cta.shared::cta.b64 P, [%0], %1, 0x989680;\n\t" \
        "@P bra.uni WD%=;\n\t bra.uni WL%=;\n\t WD%=: }" :: "r"(_m), "r"(_p) : "memory"); \
} while (0)
#define FENCE_ASYNC() asm volatile("fence.proxy.async.shared::cta;" ::: "memory")
#define BULK_CP(dst, src, sz, mb)                                                              \
    asm volatile("cp.async.bulk.shared::cta.global.mbarrier::complete_tx::bytes [%0], [%1], %2, [%3];" \
        :: "r"(dst), "l"(src), "r"(sz), "r"(mb) : "memory")
#define MMA_F16(d, a, b0v, b1v)                                                            \
    asm volatile(                                                                          \
        "mma.sync.aligned.m16n8k16.row.col.f32.f16.f16.f32 "                               \
        "{%0,%1,%2,%3}, {%4,%5,%6,%7}, {%8,%9}, {%0,%1,%2,%3};"                            \
        : "+f"(d[0]), "+f"(d[1]), "+f"(d[2]), "+f"(d[3])                                   \
        : "r"(a.x), "r"(a.y), "r"(a.z), "r"(a.w), "r"(b0v), "r"(b1v))

// -------- prep 1: style (z=0) | wsq (z=1) | wfA 9-tap-per-thread (z=2) ------
__global__ void k_prep1(const float* __restrict__ style, const float* __restrict__ mod_w,
                        const float* __restrict__ mod_b, const float* __restrict__ weight) {
    if (blockIdx.z == 0) {
        __shared__ float ss[SS];
        const int b = blockIdx.x, lane = threadIdx.x & 31, warp = threadIdx.x >> 5;
        const int ci = blockIdx.y * 8 + warp;
        for (int i = threadIdx.x; i < SS; i += 256) ss[i] = style[b * SS + i];
        __syncthreads();
        const float* wr = mod_w + (size_t)ci * SS;
        float p = 0.f;
        #pragma unroll 4
        for (int j = lane; j < SS; j += 32) p = fmaf(wr[j], ss[j], p);
        #pragma unroll
        for (int o = 16; o > 0; o >>= 1) p += __shfl_xor_sync(0xffffffffu, p, o);
        if (lane == 0) g_s[b * CIN + ci] = p + mod_b[ci];
    } else if (blockIdx.z == 1) {
        int idx = (blockIdx.x * 64 + blockIdx.y) * 256 + threadIdx.x;  // 0..262143
        const float* w = weight + (size_t)idx * 9;
        float s = 0.f;
        #pragma unroll
        for (int k = 0; k < 9; k++) s = fmaf(w[k], w[k], s);
        g_wsq[idx] = s;
    } else {
        // wfA: one thread = one (co, ci-pair), all 9 taps.
        int bid = blockIdx.x * 64 + blockIdx.y;          // 0..1023, need < 512
        if (bid >= 512) return;
        int idx = bid * 256 + threadIdx.x;               // 0..131071
        int j     = idx & 3;
        int lane  = (idx >> 2) & 31;
        int mtile = (idx >> 7) & 3;
        int wm    = (idx >> 9) & 1;
        int chunk = (idx >> 10) & 31;
        int mt    = idx >> 15;
        int g = lane >> 2, tt = lane & 3;
        int co = mt * 128 + wm * 64 + mtile * 16 + g + (j & 1) * 8;
        int ci = chunk * 16 + 2 * tt + (j >> 1) * 8;
        const float* wp = weight + ((size_t)co * CIN + ci) * 9;
        float w0[9], w1[9];
        #pragma unroll
        for (int t = 0; t < 9; t++) w0[t] = __ldg(wp + t);
        #pragma unroll
        for (int t = 0; t < 9; t++) w1[t] = __ldg(wp + 9 + t);
        uint32_t base = ((uint32_t)(mt * 32 + chunk) * 9) * 1024
                        + wm * 512 + mtile * 128 + lane * 4 + j;
        #pragma unroll
        for (int t = 0; t < 9; t++) {
            __half2 h = __floats2half2_rn(w0[t], w1[t]);
            g_wfA[base + (uint32_t)t * 1024] = *(uint32_t*)&h;
        }
    }
}

// -------- prep 2: k_inh (z<16, float4 loads) | demod (z==16, 1024 blocks) ---
__global__ void k_prep2(const float* __restrict__ input) {
    if (blockIdx.z == 16) {
        // demod: 1024 active blocks x 8 warps = 8192 (b,co) warps
        int bid = blockIdx.y * 66 + blockIdx.x;       // 0..2111
        if (bid >= 1024) return;
        int wid = bid * 8 + (threadIdx.x >> 5);       // 0..8191
        int lane = threadIdx.x & 31;
        int b = wid >> 9, co = wid & 511;
        const float* wsq = g_wsq + (size_t)co * CIN;
        const float* sr = g_s + (size_t)b * CIN;
        float p = 0.f;
        #pragma unroll 4
        for (int j = lane; j < CIN; j += 32) { float sv = sr[j]; p = fmaf(wsq[j], sv * sv, p); }
        #pragma unroll
        for (int o = 16; o > 0; o >>= 1) p += __shfl_xor_sync(0xffffffffu, p, o);
        if (lane == 0) g_demod[b * COUT + co] = rsqrtf(SCALE2 * p + 1e-8f);
        return;
    }
    // k_inh: modulated input -> fp16 chunk-major, 12-word rows (PROVEN layout).
    // Staging: one float4 load per thread (16 ci x 16 xq = full 16x64 tile).
    __shared__ float sm[16][64];
    const int yp = blockIdx.x;      // 0..65 (rows 0 and 65 are zero borders)
    const int chunk = blockIdx.y;   // 0..31
    const int b = blockIdx.z;       // 0..15
    const int tid = threadIdx.x;
    uint32_t* dst = g_inh + (((size_t)(b * 32 + chunk) * 66 + yp) * 792);
    const bool border = (yp == 0 || yp == 65);

    if (!border) {
        const int y = yp - 1;
        const int ci = tid >> 4, xq = tid & 15;
        const float sv = __ldg(g_s + b * CIN + chunk * 16 + ci);
        const float4 v = *(const float4*)(input
            + (((size_t)(b * CIN + chunk * 16 + ci)) << 12) + y * 64 + xq * 4);
        sm[ci][xq * 4 + 0] = v.x * sv;
        sm[ci][xq * 4 + 1] = v.y * sv;
        sm[ci][xq * 4 + 2] = v.z * sv;
        sm[ci][xq * 4 + 3] = v.w * sv;
        __syncthreads();
    }
    // 66 rows x 3 uint4 = 198 vector stores (12-word rows, proven)
    for (int i = tid; i < 198; i += 256) {
        const int xh = i / 3, q = i - xh * 3;
        uint32_t w[4];
        #pragma unroll
        for (int k = 0; k < 4; k++) {
            const int j = q * 4 + k;
            w[k] = 0u;
            if (!border && j < 8 && xh >= 1 && xh <= 64) {
                __half2 h = __floats2half2_rn(sm[2 * j][xh - 1], sm[2 * j + 1][xh - 1]);
                w[k] = *(uint32_t*)&h;
            }
        }
        *(uint4*)(dst + xh * 12 + q * 4) = make_uint4(w[0], w[1], w[2], w[3]);
    }
}

// ---------------- main conv: fp16 mma.sync implicit GEMM (R15 champion) -----
// CTA: 128 co (mt) x 128 px (2 rows x 64 cols), 256 threads, 8 warps 2m x 4n.
// B smem rows are 12 words -> bank index (12g + tt) mod 32 hits all 32 banks.
#define NCHUNK 32
#define A_SLAB 36864               // 9*2*4*128*4 bytes
#define B_SLAB 12672               // 4 rows * 66 px * 12 words * 4B
#define OFF_A 64
#define OFF_B (OFF_A + 2 * A_SLAB)          // 73792
#define SMEM_TOTAL (OFF_B + 2 * B_SLAB)     // 99136

__global__ void __launch_bounds__(256, 2)
k_conv(float* __restrict__ out) {
    extern __shared__ char smem[];
    const uint32_t sb = smem_u32(smem);
    const int tid = threadIdx.x, lane = tid & 31, wid = tid >> 5;
    const int wm = wid >> 2, wn = wid & 3;
    const int yl = wn >> 1, xw = (wn & 1) * 32;
    const int g = lane >> 2, tt = lane & 3;

    const int mt = blockIdx.x;
    const int y0 = blockIdx.y * 2;
    const int b  = blockIdx.z;

    if (tid == 0) { MBAR_INIT(sb + 0, 1); MBAR_INIT(sb + 8, 1); }
    __syncthreads();

    const uint32_t* gA = g_wfA + (size_t)mt * 32 * 9216;
    const uint32_t* gB = g_inh + (size_t)b * 32 * 66 * 792;

    if (tid == 0) {
        FENCE_ASYNC();
        #pragma unroll
        for (int k = 0; k < 2; k++) {
            uint32_t mb = sb + k * 8;
            MBAR_EXPECT(mb, A_SLAB + B_SLAB);
            BULK_CP(sb + OFF_A + k * A_SLAB, (const void*)(gA + (size_t)k * 9216), A_SLAB, mb);
            BULK_CP(sb + OFF_B + k * B_SLAB, (const void*)(gB + ((size_t)k * 66 + y0) * 792), B_SLAB, mb);
        }
    }

    float acc[4][4][4];
    #pragma unroll
    for (int m = 0; m < 4; m++)
        #pragma unroll
        for (int n = 0; n < 4; n++)
            #pragma unroll
            for (int c = 0; c < 4; c++) acc[m][n][c] = 0.f;

    for (int c = 0; c < NCHUNK; c++) {
        MBAR_WAIT(sb + (c & 1) * 8, (c >> 1) & 1);
        const uint32_t* sA = (const uint32_t*)(smem + OFF_A + (c & 1) * A_SLAB);
        const uint32_t* sB = (const uint32_t*)(smem + OFF_B + (c & 1) * B_SLAB);

        #pragma unroll
        for (int tap = 0; tap < 9; tap++) {
            const int dy = tap / 3, dx = tap % 3;
            const int r = yl + dy;
            const uint32_t* ap = sA + (tap * 2 + wm) * 512 + lane * 4;
            uint4 A0 = *(const uint4*)(ap);
            uint4 A1 = *(const uint4*)(ap + 128);
            uint4 A2 = *(const uint4*)(ap + 256);
            uint4 A3 = *(const uint4*)(ap + 384);
            const uint32_t* bp = sB + (size_t)(r * 66 + xw + dx + g) * 12 + tt;
            #pragma unroll
            for (int nf = 0; nf < 4; nf++) {
                uint32_t b0 = bp[nf * 96];
                uint32_t b1 = bp[nf * 96 + 4];
                MMA_F16(acc[0][nf], A0, b0, b1);
                MMA_F16(acc[1][nf], A1, b0, b1);
                MMA_F16(acc[2][nf], A2, b0, b1);
                MMA_F16(acc[3][nf], A3, b0, b1);
            }
        }
        __syncthreads();
        if (tid == 0 && c + 2 < NCHUNK) {
            const int k = c + 2;
            uint32_t mb = sb + (k & 1) * 8;
            MBAR_EXPECT(mb, A_SLAB + B_SLAB);
            BULK_CP(sb + OFF_A + (k & 1) * A_SLAB, (const void*)(gA + (size_t)k * 9216), A_SLAB, mb);
            BULK_CP(sb + OFF_B + (k & 1) * B_SLAB, (const void*)(gB + ((size_t)k * 66 + y0) * 792), B_SLAB, mb);
        }
    }

    // ---- epilogue: scale * demod, float2 stores ----
    const float scale = rsqrtf(4608.0f);
    const int y = y0 + yl;
    #pragma unroll
    for (int im = 0; im < 4; im++) {
        const int coA = mt * 128 + wm * 64 + im * 16 + g;
        const float fA = g_demod[b * COUT + coA] * scale;
        const float fB = g_demod[b * COUT + coA + 8] * scale;
        const size_t base = ((((size_t)b * COUT + coA) << 6) + y) << 6;
        #pragma unroll
        for (int nf = 0; nf < 4; nf++) {
            const int x = xw + nf * 8 + 2 * tt;
            float2 lo = make_float2(acc[im][nf][0] * fA, acc[im][nf][1] * fA);
            float2 hi = make_float2(acc[im][nf][2] * fB, acc[im][nf][3] * fB);
            *(float2*)(out + base + x) = lo;
            *(float2*)(out + base + ((size_t)8 << 12) + x) = hi;   // co+8 plane
        }
    }
}

// ---------------------------------------------------------------------------
extern "C" void kernel_launch(void* const* d_in, const int* in_sizes, int n_in,
                              void* d_out, int out_size) {
    const float* input  = (const float*)d_in[0];
    const float* style  = (const float*)d_in[1];
    const float* weight = (const float*)d_in[2];
    const float* mod_w  = (const float*)d_in[3];
    const float* mod_b  = (const float*)d_in[4];
    float* out = (float*)d_out;

    static int smem_set = 0;
    if (!smem_set) {
        cudaFuncSetAttribute(k_conv, cudaFuncAttributeMaxDynamicSharedMemorySize, SMEM_TOTAL);
        smem_set = 1;
    }

    k_prep1<<<dim3(16, 64, 3), 256>>>(style, mod_w, mod_b, weight);
    k_prep2<<<dim3(66, 32, 17), 256>>>(input);
    k_conv<<<dim3(4, 32, 16), 256, SMEM_TOTAL>>>(out);
}